// round 5
// baseline (speedup 1.0000x reference)
#include <cuda_runtime.h>
#include <cuda_bf16.h>
#include <mma.h>
#include <cstddef>

using namespace nvcuda;
typedef __nv_bfloat16 bf16;

#define D    512
#define H    8
#define DK   64
#define TT   128
#define BBATCH 8
#define NL   6
#define VV   32000
#define FF   2048
#define MROWS (BBATCH*TT)
#define MD   (MROWS*D)

#define N_EA  (NL*4*D*D)
#define N_EF1 (NL*D*FF)
#define N_EF2 (NL*FF*D)
#define N_DA  (NL*8*D*D)
#define N_DF1 (NL*D*FF)
#define N_DF2 (NL*FF*D)
#define N_EMB (VV*D)
#define OFF_EA   0
#define OFF_EF1  (OFF_EA + N_EA)
#define OFF_EF2  (OFF_EF1 + N_EF1)
#define OFF_DA   (OFF_EF2 + N_EF2)
#define OFF_DF1  (OFF_DA + N_DA)
#define OFF_DF2  (OFF_DF1 + N_DF1)
#define OFF_EMB  (OFF_DF2 + N_DF2)
#define WPOOL_N  (OFF_EMB + N_EMB)

__device__ float g_x  [MD];
__device__ bf16  g_qkv[3*MD];
__device__ bf16  g_hb [MD];
__device__ bf16  g_aob[MD];
__device__ bf16  g_memb[MD];
__device__ bf16  g_ffnb[MROWS*FF];
__device__ bf16  g_kc [NL*MD];
__device__ bf16  g_vc [NL*MD];
__device__ bf16  g_wpool[WPOOL_N];

// ---------------- cp.async helpers ----------------
__device__ __forceinline__ void cpa16(void* dst, const void* src) {
    unsigned sdst = (unsigned)__cvta_generic_to_shared(dst);
    asm volatile("cp.async.cg.shared.global [%0], [%1], 16;\n" :: "r"(sdst), "l"(src));
}
__device__ __forceinline__ void cpa_commit() { asm volatile("cp.async.commit_group;\n"); }
template<int N>
__device__ __forceinline__ void cpa_wait() { asm volatile("cp.async.wait_group %0;\n" :: "n"(N)); }

// ---------------- fp32 -> bf16 ----------------
__global__ void f2b_kernel(const float* __restrict__ s, bf16* __restrict__ d, int n4) {
    int i = blockIdx.x * blockDim.x + threadIdx.x;
    if (i >= n4) return;
    float4 v = reinterpret_cast<const float4*>(s)[i];
    __nv_bfloat162* o = reinterpret_cast<__nv_bfloat162*>(d) + 2 * i;
    o[0] = __floats2bfloat162_rn(v.x, v.y);
    o[1] = __floats2bfloat162_rn(v.z, v.w);
}

// ---------------- embedding ----------------
__global__ void embed_kernel(const int* __restrict__ tok,
                             const float* __restrict__ tok_emb,
                             const float* __restrict__ pos_emb,
                             float* __restrict__ out) {
    int idx = blockIdx.x * blockDim.x + threadIdx.x;
    if (idx >= MROWS * D) return;
    int row = idx / D, d = idx % D;
    int t = row % TT;
    out[idx] = tok_emb[(size_t)tok[row] * D + d] + pos_emb[(size_t)t * D + d];
}

// ---------------- layernorm: warp per row, 8 rows/block ----------------
__global__ __launch_bounds__(256) void ln_kernel(const float* __restrict__ x,
                          const float* __restrict__ g,
                          const float* __restrict__ b,
                          bf16* __restrict__ out) {
    int row  = blockIdx.x * 8 + (threadIdx.x >> 5);
    int lane = threadIdx.x & 31;
    const float4* xr = reinterpret_cast<const float4*>(x + (size_t)row * D);

    float4 v[4];
    float s = 0.f;
    #pragma unroll
    for (int j = 0; j < 4; j++) {
        v[j] = xr[lane + j * 32];
        s += v[j].x + v[j].y + v[j].z + v[j].w;
    }
    #pragma unroll
    for (int o = 16; o; o >>= 1) s += __shfl_xor_sync(0xffffffffu, s, o);
    float mu = s * (1.f / D);

    float var = 0.f;
    #pragma unroll
    for (int j = 0; j < 4; j++) {
        float a0 = v[j].x - mu, a1 = v[j].y - mu, a2 = v[j].z - mu, a3 = v[j].w - mu;
        var += a0 * a0 + a1 * a1 + a2 * a2 + a3 * a3;
    }
    #pragma unroll
    for (int o = 16; o; o >>= 1) var += __shfl_xor_sync(0xffffffffu, var, o);
    float inv = rsqrtf(var * (1.f / D) + 1e-6f);

    const float4* g4 = reinterpret_cast<const float4*>(g);
    const float4* b4 = reinterpret_cast<const float4*>(b);
    uint2* o8 = reinterpret_cast<uint2*>(out + (size_t)row * D);
    #pragma unroll
    for (int j = 0; j < 4; j++) {
        int c = lane + j * 32;
        float4 gg = g4[c], bb = b4[c];
        float r0 = (v[j].x - mu) * inv * gg.x + bb.x;
        float r1 = (v[j].y - mu) * inv * gg.y + bb.y;
        float r2 = (v[j].z - mu) * inv * gg.z + bb.z;
        float r3 = (v[j].w - mu) * inv * gg.w + bb.w;
        __nv_bfloat162 lo = __floats2bfloat162_rn(r0, r1);
        __nv_bfloat162 hi = __floats2bfloat162_rn(r2, r3);
        uint2 pk; pk.x = *reinterpret_cast<unsigned*>(&lo); pk.y = *reinterpret_cast<unsigned*>(&hi);
        o8[c] = pk;
    }
}

// ---------------- bf16 tensor-core GEMM, 4-stage cp.async pipeline ----------------
#define ASTR 40
#define BSTR0 72
#define BSTR1 40
#define BELEM 2560                 // max B stage elems (64*40 or 32*72=2304)
#define NSTG 4

// dynamic smem bytes per MT
#define GSMEM(MT) (NSTG * ((MT) * ASTR + BELEM) * 2)

template<int TB, int OB, int MT>
__global__ __launch_bounds__(256) void wgemm(
        const bf16* __restrict__ Ag, const bf16* __restrict__ Bg,
        const float* __restrict__ bias, const float* __restrict__ res,
        void* __restrict__ Cv, int M, int N, int K, int relu,
        size_t sA, size_t sB, size_t sBias, size_t sC) {
    constexpr int WSM = MT / 32;
    constexpr int WSN = 8 / WSM;
    constexpr int NFR = 64 / (WSN * 16);
    constexpr int ASZ = MT * ASTR;
    constexpr int STG = ASZ + BELEM;   // elems per stage

    const int z = blockIdx.z;
    const bf16* A = Ag + (size_t)z * sA;
    const bf16* B = Bg + (size_t)z * sB;
    const float* bi = bias ? bias + (size_t)z * sBias : nullptr;

    extern __shared__ __align__(16) char smem_raw[];
    bf16*  Sbase = reinterpret_cast<bf16*>(smem_raw);
    float* Cs    = reinterpret_cast<float*>(smem_raw);

    const int tid  = threadIdx.x;
    const int warp = tid >> 5;
    const int wm   = warp % WSM;
    const int wn   = warp / WSM;
    const int wnoff = wn * 16 * NFR;
    const int m0 = blockIdx.y * MT, n0 = blockIdx.x * 64;

    wmma::fragment<wmma::accumulator, 16, 16, 16, float> acc[2][NFR];
    #pragma unroll
    for (int i = 0; i < 2; i++)
        #pragma unroll
        for (int j = 0; j < NFR; j++) wmma::fill_fragment(acc[i][j], 0.f);

    auto load_stage = [&](int s, int k0) {
        bf16* As = Sbase + s * STG;
        bf16* Bs = As + ASZ;
        #pragma unroll
        for (int it = 0; it < MT / 64; it++) {
            int chunk = tid + it * 256;
            int r = chunk >> 2, c = (chunk & 3) << 3;
            cpa16(&As[r * ASTR + c], &A[(size_t)(m0 + r) * K + k0 + c]);
        }
        if (TB == 0) {
            int r = tid >> 3, c = (tid & 7) << 3;
            cpa16(&Bs[r * BSTR0 + c], &B[(size_t)(k0 + r) * N + n0 + c]);
        } else {
            int r = tid >> 2, c = (tid & 3) << 3;
            cpa16(&Bs[r * BSTR1 + c], &B[(size_t)(n0 + r) * K + k0 + c]);
        }
        cpa_commit();
    };

    auto compute_stage = [&](int s) {
        bf16* As = Sbase + s * STG;
        bf16* Bs = As + ASZ;
        #pragma unroll
        for (int kk = 0; kk < 32; kk += 16) {
            wmma::fragment<wmma::matrix_a, 16, 16, 16, bf16, wmma::row_major> a0, a1;
            wmma::load_matrix_sync(a0, &As[(wm * 32 +  0) * ASTR + kk], ASTR);
            wmma::load_matrix_sync(a1, &As[(wm * 32 + 16) * ASTR + kk], ASTR);
            #pragma unroll
            for (int j = 0; j < NFR; j++) {
                if (TB == 0) {
                    wmma::fragment<wmma::matrix_b, 16, 16, 16, bf16, wmma::row_major> bf;
                    wmma::load_matrix_sync(bf, &Bs[kk * BSTR0 + wnoff + j * 16], BSTR0);
                    wmma::mma_sync(acc[0][j], a0, bf, acc[0][j]);
                    wmma::mma_sync(acc[1][j], a1, bf, acc[1][j]);
                } else {
                    wmma::fragment<wmma::matrix_b, 16, 16, 16, bf16, wmma::col_major> bf;
                    wmma::load_matrix_sync(bf, &Bs[(wnoff + j * 16) * BSTR1 + kk], BSTR1);
                    wmma::mma_sync(acc[0][j], a0, bf, acc[0][j]);
                    wmma::mma_sync(acc[1][j], a1, bf, acc[1][j]);
                }
            }
        }
    };

    const int KT = K >> 5;   // >= 16 always here
    load_stage(0, 0);
    load_stage(1, 32);
    load_stage(2, 64);

    for (int kt = 0; kt < KT; kt++) {
        if (kt < KT - 2)       cpa_wait<NSTG - 2>();
        else if (kt == KT - 2) cpa_wait<1>();
        else                   cpa_wait<0>();
        __syncthreads();
        if (kt + NSTG - 1 < KT) load_stage((kt + NSTG - 1) & (NSTG - 1), (kt + NSTG - 1) << 5);
        compute_stage(kt & (NSTG - 1));
    }
    __syncthreads();   // all compute done before epilogue aliases smem

    #pragma unroll
    for (int i = 0; i < 2; i++)
        #pragma unroll
        for (int j = 0; j < NFR; j++)
            wmma::store_matrix_sync(&Cs[(wm * 32 + i * 16) * 72 + wnoff + j * 16],
                                    acc[i][j], 72, wmma::mem_row_major);
    __syncthreads();

    #pragma unroll
    for (int it = 0; it < MT / 4; it++) {
        int idx = tid + it * 256;
        int r = idx >> 6, c = idx & 63;
        int m = m0 + r, n = n0 + c;
        float val = Cs[r * 72 + c];
        if (bi)   val += bi[n];
        if (relu) val = fmaxf(val, 0.f);
        if (OB) {
            reinterpret_cast<bf16*>(Cv)[(size_t)z * sC + (size_t)m * N + n] = __float2bfloat16(val);
        } else {
            float* C = reinterpret_cast<float*>(Cv) + (size_t)z * sC;
            if (res) val += res[(size_t)m * N + n];
            C[(size_t)m * N + n] = val;
        }
    }
}

// ---------------- fused flash attention ----------------
#define FA_SMEM 79872

__global__ __launch_bounds__(256) void flash_kernel(
        const bf16* __restrict__ Q, const bf16* __restrict__ Kp, const bf16* __restrict__ Vp,
        const int* __restrict__ toks, int causal, bf16* __restrict__ out) {
    extern __shared__ __align__(16) char sm[];
    bf16*  Qs = reinterpret_cast<bf16*>(sm);
    bf16*  Ks = Qs + 64 * 72;
    bf16*  Vs = Ks + 128 * 72;
    float* S  = reinterpret_cast<float*>(sm + 46080);
    bf16*  Pb = reinterpret_cast<bf16*>(sm);
    __shared__ int msk[TT];

    const int q0 = blockIdx.x * 64;
    const int h  = blockIdx.y;
    const int b  = blockIdx.z;
    const int tid = threadIdx.x, warp = tid >> 5, lane = tid & 31;

    for (int ch = tid; ch < 512; ch += 256) {
        int r = ch >> 3, c = (ch & 7) << 3;
        *reinterpret_cast<uint4*>(&Qs[r * 72 + c]) =
            *reinterpret_cast<const uint4*>(&Q[(size_t)(b * TT + q0 + r) * D + h * DK + c]);
    }
    for (int ch = tid; ch < 1024; ch += 256) {
        int r = ch >> 3, c = (ch & 7) << 3;
        *reinterpret_cast<uint4*>(&Ks[r * 72 + c]) =
            *reinterpret_cast<const uint4*>(&Kp[(size_t)(b * TT + r) * D + h * DK + c]);
        *reinterpret_cast<uint4*>(&Vs[r * 72 + c]) =
            *reinterpret_cast<const uint4*>(&Vp[(size_t)(b * TT + r) * D + h * DK + c]);
    }
    if (tid < TT) msk[tid] = (toks[b * TT + tid] == 1);
    __syncthreads();

    {
        int wm = warp & 3, wn = warp >> 2;
        #pragma unroll
        for (int n = 0; n < 4; n++) {
            wmma::fragment<wmma::accumulator, 16, 16, 16, float> acc;
            wmma::fill_fragment(acc, 0.f);
            #pragma unroll
            for (int kk = 0; kk < 4; kk++) {
                wmma::fragment<wmma::matrix_a, 16, 16, 16, bf16, wmma::row_major> a;
                wmma::fragment<wmma::matrix_b, 16, 16, 16, bf16, wmma::col_major> bb;
                wmma::load_matrix_sync(a, &Qs[(wm * 16) * 72 + kk * 16], 72);
                wmma::load_matrix_sync(bb, &Ks[(wn * 64 + n * 16) * 72 + kk * 16], 72);
                wmma::mma_sync(acc, a, bb, acc);
            }
            wmma::store_matrix_sync(&S[(wm * 16) * 132 + wn * 64 + n * 16], acc, 132,
                                    wmma::mem_row_major);
        }
    }
    __syncthreads();

    for (int rr = 0; rr < 8; rr++) {
        int r = warp * 8 + rr;
        int qg = q0 + r;
        float v[4];
        #pragma unroll
        for (int j = 0; j < 4; j++) {
            int col = lane + j * 32;
            float s = S[r * 132 + col] * 0.125f;
            if (msk[col] || (causal && col > qg)) s = -1e30f;
            v[j] = s;
        }
        float m = fmaxf(fmaxf(v[0], v[1]), fmaxf(v[2], v[3]));
        #pragma unroll
        for (int o = 16; o; o >>= 1) m = fmaxf(m, __shfl_xor_sync(0xffffffffu, m, o));
        float e[4], sum = 0.f;
        #pragma unroll
        for (int j = 0; j < 4; j++) { e[j] = __expf(v[j] - m); sum += e[j]; }
        #pragma unroll
        for (int o = 16; o; o >>= 1) sum += __shfl_xor_sync(0xffffffffu, sum, o);
        float inv = __frcp_rn(sum);
        #pragma unroll
        for (int j = 0; j < 4; j++)
            Pb[r * 136 + lane + j * 32] = __float2bfloat16(e[j] * inv);
    }
    __syncthreads();

    {
        int wm = warp & 3, wn = warp >> 2;
        #pragma unroll
        for (int n = 0; n < 2; n++) {
            wmma::fragment<wmma::accumulator, 16, 16, 16, float> acc;
            wmma::fill_fragment(acc, 0.f);
            #pragma unroll
            for (int kk = 0; kk < 8; kk++) {
                wmma::fragment<wmma::matrix_a, 16, 16, 16, bf16, wmma::row_major> a;
                wmma::fragment<wmma::matrix_b, 16, 16, 16, bf16, wmma::row_major> bb;
                wmma::load_matrix_sync(a, &Pb[(wm * 16) * 136 + kk * 16], 136);
                wmma::load_matrix_sync(bb, &Vs[(kk * 16) * 72 + wn * 32 + n * 16], 72);
                wmma::mma_sync(acc, a, bb, acc);
            }
            wmma::store_matrix_sync(&S[(wm * 16) * 132 + wn * 32 + n * 16], acc, 132,
                                    wmma::mem_row_major);
        }
    }
    __syncthreads();

    for (int idx = tid; idx < 64 * 64; idx += 256) {
        int r = idx >> 6, c = idx & 63;
        out[(size_t)(b * TT + q0 + r) * D + h * DK + c] = __float2bfloat16(S[r * 132 + c]);
    }
}

// ---------------- log_softmax (online, 512 threads) ----------------
__global__ __launch_bounds__(512) void logsoftmax_kernel(float* __restrict__ logits) {
    int row = blockIdx.x;
    float* x = logits + (size_t)row * VV;
    __shared__ float shm[512], shs[512];
    int tid = threadIdx.x;

    float m = -1e30f, s = 0.f;
    for (int i = tid; i < VV / 4; i += 512) {
        float4 v = reinterpret_cast<const float4*>(x)[i];
        float cm = fmaxf(fmaxf(v.x, v.y), fmaxf(v.z, v.w));
        if (cm > m) { s *= __expf(m - cm); m = cm; }
        s += __expf(v.x - m) + __expf(v.y - m) + __expf(v.z - m) + __expf(v.w - m);
    }
    shm[tid] = m; shs[tid] = s; __syncthreads();
    for (int o = 256; o; o >>= 1) {
        if (tid < o) {
            float m2 = shm[tid + o], s2 = shs[tid + o];
            float mn = fmaxf(shm[tid], m2);
            shs[tid] = shs[tid] * __expf(shm[tid] - mn) + s2 * __expf(m2 - mn);
            shm[tid] = mn;
        }
        __syncthreads();
    }
    float lse = shm[0] + logf(shs[0]);

    for (int i = tid; i < VV / 4; i += 512) {
        float4 v = reinterpret_cast<float4*>(x)[i];
        v.x -= lse; v.y -= lse; v.z -= lse; v.w -= lse;
        reinterpret_cast<float4*>(x)[i] = v;
    }
}

// ---------------- host helpers ----------------
static void G(const bf16* A, const bf16* B, const float* bias, const float* res,
              void* C, int M, int N, int K, int relu, int tb, int ob, int mt, int batch,
              size_t sA, size_t sB, size_t sBias, size_t sC) {
    dim3 grid(N / 64, M / mt, batch);
    if (tb)
        wgemm<1, 0, 128><<<grid, 256, GSMEM(128)>>>(A, B, bias, res, C, M, N, K, relu, sA, sB, sBias, sC);
    else if (ob && mt == 128)
        wgemm<0, 1, 128><<<grid, 256, GSMEM(128)>>>(A, B, bias, res, C, M, N, K, relu, sA, sB, sBias, sC);
    else if (ob)
        wgemm<0, 1, 64><<<grid, 256, GSMEM(64)>>>(A, B, bias, res, C, M, N, K, relu, sA, sB, sBias, sC);
    else
        wgemm<0, 0, 64><<<grid, 256, GSMEM(64)>>>(A, B, bias, res, C, M, N, K, relu, sA, sB, sBias, sC);
}

static void CVT(const float* s, bf16* d, size_t n) {
    int n4 = (int)(n / 4);
    f2b_kernel<<<(n4 + 255) / 256, 256>>>(s, d, n4);
}

extern "C" void kernel_launch(void* const* d_in, const int* in_sizes, int n_in,
                              void* d_out, int out_size) {
    const int*   src        = (const int*)  d_in[0];
    const int*   tgt        = (const int*)  d_in[1];
    const float* tok_emb    = (const float*)d_in[2];
    const float* pos_emb    = (const float*)d_in[3];
    const float* enc_attn_w = (const float*)d_in[4];
    const float* enc_attn_b = (const float*)d_in[5];
    const float* enc_ffn_w1 = (const float*)d_in[6];
    const float* enc_ffn_b1 = (const float*)d_in[7];
    const float* enc_ffn_w2 = (const float*)d_in[8];
    const float* enc_ffn_b2 = (const float*)d_in[9];
    const float* enc_ln     = (const float*)d_in[10];
    const float* enc_fln    = (const float*)d_in[11];
    const float* dec_attn_w = (const float*)d_in[12];
    const float* dec_attn_b = (const float*)d_in[13];
    const float* dec_ffn_w1 = (const float*)d_in[14];
    const float* dec_ffn_b1 = (const float*)d_in[15];
    const float* dec_ffn_w2 = (const float*)d_in[16];
    const float* dec_ffn_b2 = (const float*)d_in[17];
    const float* dec_ln     = (const float*)d_in[18];
    const float* dec_fln    = (const float*)d_in[19];
    float* out = (float*)d_out;

    float *x;
    bf16 *qkv, *hb, *aob, *memb, *ffnb, *kc, *vc, *wp;
    cudaGetSymbolAddress((void**)&x,    g_x);
    cudaGetSymbolAddress((void**)&qkv,  g_qkv);
    cudaGetSymbolAddress((void**)&hb,   g_hb);
    cudaGetSymbolAddress((void**)&aob,  g_aob);
    cudaGetSymbolAddress((void**)&memb, g_memb);
    cudaGetSymbolAddress((void**)&ffnb, g_ffnb);
    cudaGetSymbolAddress((void**)&kc,   g_kc);
    cudaGetSymbolAddress((void**)&vc,   g_vc);
    cudaGetSymbolAddress((void**)&wp,   g_wpool);

    cudaFuncSetAttribute(flash_kernel, cudaFuncAttributeMaxDynamicSharedMemorySize, FA_SMEM);
    cudaFuncSetAttribute((const void*)wgemm<1, 0, 128>, cudaFuncAttributeMaxDynamicSharedMemorySize, GSMEM(128));
    cudaFuncSetAttribute((const void*)wgemm<0, 1, 128>, cudaFuncAttributeMaxDynamicSharedMemorySize, GSMEM(128));
    cudaFuncSetAttribute((const void*)wgemm<0, 1, 64>,  cudaFuncAttributeMaxDynamicSharedMemorySize, GSMEM(64));
    cudaFuncSetAttribute((const void*)wgemm<0, 0, 64>,  cudaFuncAttributeMaxDynamicSharedMemorySize, GSMEM(64));

    const size_t DD = (size_t)D * D;
    dim3 fgrid(TT / 64, H, BBATCH);

    CVT(enc_attn_w, wp + OFF_EA,  N_EA);
    CVT(enc_ffn_w1, wp + OFF_EF1, N_EF1);
    CVT(enc_ffn_w2, wp + OFF_EF2, N_EF2);
    CVT(dec_attn_w, wp + OFF_DA,  N_DA);
    CVT(dec_ffn_w1, wp + OFF_DF1, N_DF1);
    CVT(dec_ffn_w2, wp + OFF_DF2, N_DF2);
    CVT(tok_emb,    wp + OFF_EMB, N_EMB);

    // ================= encoder =================
    embed_kernel<<<(MROWS * D + 255) / 256, 256>>>(src, tok_emb, pos_emb, x);
    for (int i = 0; i < NL; i++) {
        const bf16*  W   = wp + OFF_EA + (size_t)i * 4 * DD;
        const float* Wb  = enc_attn_b + (size_t)i * 4 * D;
        const float* lnp = enc_ln + (size_t)i * 4 * D;

        ln_kernel<<<MROWS / 8, 256>>>(x, lnp, lnp + D, hb);
        G(hb, W, Wb, nullptr, qkv, MROWS, D, D, 0, 0, 1, 128, 3, 0, DD, D, MD);
        flash_kernel<<<fgrid, 256, FA_SMEM>>>(qkv, qkv + MD, qkv + 2 * MD, src, 0, aob);
        G(aob, W + 3 * DD, Wb + 3 * D, x, x, MROWS, D, D, 0, 0, 0, 64, 1, 0, 0, 0, 0);

        ln_kernel<<<MROWS / 8, 256>>>(x, lnp + 2 * D, lnp + 3 * D, hb);
        G(hb, wp + OFF_EF1 + (size_t)i * D * FF, enc_ffn_b1 + (size_t)i * FF,
          nullptr, ffnb, MROWS, FF, D, 1, 0, 1, 128, 1, 0, 0, 0, 0);
        G(ffnb, wp + OFF_EF2 + (size_t)i * FF * D, enc_ffn_b2 + (size_t)i * D,
          x, x, MROWS, D, FF, 0, 0, 0, 64, 1, 0, 0, 0, 0);
    }
    ln_kernel<<<MROWS / 8, 256>>>(x, enc_fln, enc_fln + D, memb);

    // cross-attention K/V for all decoder layers (batched over layers)
    G(memb, wp + OFF_DA + 5 * DD, dec_attn_b + 5 * D, nullptr, kc,
      MROWS, D, D, 0, 0, 1, 128, NL, 0, 8 * DD, 8 * D, MD);
    G(memb, wp + OFF_DA + 6 * DD, dec_attn_b + 6 * D, nullptr, vc,
      MROWS, D, D, 0, 0, 1, 128, NL, 0, 8 * DD, 8 * D, MD);

    // ================= decoder =================
    embed_kernel<<<(MROWS * D + 255) / 256, 256>>>(tgt, tok_emb, pos_emb, x);
    for (int i = 0; i < NL; i++) {
        const bf16*  W   = wp + OFF_DA + (size_t)i * 8 * DD;
        const float* Wb  = dec_attn_b + (size_t)i * 8 * D;
        const float* lnp = dec_ln + (size_t)i * 6 * D;

        // self-attention
        ln_kernel<<<MROWS / 8, 256>>>(x, lnp, lnp + D, hb);
        G(hb, W, Wb, nullptr, qkv, MROWS, D, D, 0, 0, 1, 128, 3, 0, DD, D, MD);
        flash_kernel<<<fgrid, 256, FA_SMEM>>>(qkv, qkv + MD, qkv + 2 * MD, tgt, 1, aob);
        G(aob, W + 3 * DD, Wb + 3 * D, x, x, MROWS, D, D, 0, 0, 0, 64, 1, 0, 0, 0, 0);

        // cross-attention
        ln_kernel<<<MROWS / 8, 256>>>(x, lnp + 2 * D, lnp + 3 * D, hb);
        G(hb, W + 4 * DD, Wb + 4 * D, nullptr, qkv, MROWS, D, D, 0, 0, 1, 64, 1, 0, 0, 0, 0);
        flash_kernel<<<fgrid, 256, FA_SMEM>>>(qkv, kc + (size_t)i * MD, vc + (size_t)i * MD,
                                              src, 0, aob);
        G(aob, W + 7 * DD, Wb + 7 * D, x, x, MROWS, D, D, 0, 0, 0, 64, 1, 0, 0, 0, 0);

        // FFN
        ln_kernel<<<MROWS / 8, 256>>>(x, lnp + 4 * D, lnp + 5 * D, hb);
        G(hb, wp + OFF_DF1 + (size_t)i * D * FF, dec_ffn_b1 + (size_t)i * FF,
          nullptr, ffnb, MROWS, FF, D, 1, 0, 1, 128, 1, 0, 0, 0, 0);
        G(ffnb, wp + OFF_DF2 + (size_t)i * FF * D, dec_ffn_b2 + (size_t)i * D,
          x, x, MROWS, D, FF, 0, 0, 0, 64, 1, 0, 0, 0, 0);
    }
    ln_kernel<<<MROWS / 8, 256>>>(x, dec_fln, dec_fln + D, hb);

    // ============ generator: tied projection + log_softmax ============
    G(hb, wp + OFF_EMB, nullptr, nullptr, out, MROWS, VV, D, 0, 1, 0, 128, 1, 0, 0, 0, 0);
    logsoftmax_kernel<<<MROWS, 512>>>(out);
}

// round 6
// speedup vs baseline: 1.4466x; 1.4466x over previous
#include <cuda_runtime.h>
#include <cuda_bf16.h>
#include <mma.h>
#include <cstddef>

using namespace nvcuda;
typedef __nv_bfloat16 bf16;

#define D    512
#define H    8
#define DK   64
#define TT   128
#define BBATCH 8
#define NL   6
#define VV   32000
#define FF   2048
#define MROWS (BBATCH*TT)
#define MD   (MROWS*D)

#define N_EA  (NL*4*D*D)
#define N_EF1 (NL*D*FF)
#define N_EF2 (NL*FF*D)
#define N_DA  (NL*8*D*D)
#define N_DF1 (NL*D*FF)
#define N_DF2 (NL*FF*D)
#define N_EMB (VV*D)
#define OFF_EA   0
#define OFF_EF1  (OFF_EA + N_EA)
#define OFF_EF2  (OFF_EF1 + N_EF1)
#define OFF_DA   (OFF_EF2 + N_EF2)
#define OFF_DF1  (OFF_DA + N_DA)
#define OFF_DF2  (OFF_DF1 + N_DF1)
#define OFF_EMB  (OFF_DF2 + N_DF2)
#define WPOOL_N  (OFF_EMB + N_EMB)

__device__ float g_x  [MD];
__device__ bf16  g_qkv[3*MD];
__device__ bf16  g_hb [MD];
__device__ bf16  g_aob[MD];
__device__ bf16  g_memb[MD];
__device__ bf16  g_ffnb[MROWS*FF];
__device__ bf16  g_kc [NL*MD];
__device__ bf16  g_vc [NL*MD];
__device__ bf16  g_wpool[WPOOL_N];

// ---------------- cp.async helpers ----------------
__device__ __forceinline__ void cpa16(void* dst, const void* src) {
    unsigned sdst = (unsigned)__cvta_generic_to_shared(dst);
    asm volatile("cp.async.cg.shared.global [%0], [%1], 16;\n" :: "r"(sdst), "l"(src));
}
__device__ __forceinline__ void cpa_commit() { asm volatile("cp.async.commit_group;\n"); }
template<int N>
__device__ __forceinline__ void cpa_wait() { asm volatile("cp.async.wait_group %0;\n" :: "n"(N)); }

// ---------------- fp32 -> bf16 ----------------
__global__ void f2b_kernel(const float* __restrict__ s, bf16* __restrict__ d, int n4) {
    int i = blockIdx.x * blockDim.x + threadIdx.x;
    if (i >= n4) return;
    float4 v = reinterpret_cast<const float4*>(s)[i];
    __nv_bfloat162* o = reinterpret_cast<__nv_bfloat162*>(d) + 2 * i;
    o[0] = __floats2bfloat162_rn(v.x, v.y);
    o[1] = __floats2bfloat162_rn(v.z, v.w);
}

// ---------------- embedding ----------------
__global__ void embed_kernel(const int* __restrict__ tok,
                             const float* __restrict__ tok_emb,
                             const float* __restrict__ pos_emb,
                             float* __restrict__ out) {
    int idx = blockIdx.x * blockDim.x + threadIdx.x;
    if (idx >= MROWS * D) return;
    int row = idx / D, d = idx % D;
    int t = row % TT;
    out[idx] = tok_emb[(size_t)tok[row] * D + d] + pos_emb[(size_t)t * D + d];
}

// ---------------- layernorm: warp per row, 8 rows/block ----------------
__global__ __launch_bounds__(256) void ln_kernel(const float* __restrict__ x,
                          const float* __restrict__ g,
                          const float* __restrict__ b,
                          bf16* __restrict__ out) {
    int row  = blockIdx.x * 8 + (threadIdx.x >> 5);
    int lane = threadIdx.x & 31;
    const float4* xr = reinterpret_cast<const float4*>(x + (size_t)row * D);

    float4 v[4];
    float s = 0.f;
    #pragma unroll
    for (int j = 0; j < 4; j++) {
        v[j] = xr[lane + j * 32];
        s += v[j].x + v[j].y + v[j].z + v[j].w;
    }
    #pragma unroll
    for (int o = 16; o; o >>= 1) s += __shfl_xor_sync(0xffffffffu, s, o);
    float mu = s * (1.f / D);

    float var = 0.f;
    #pragma unroll
    for (int j = 0; j < 4; j++) {
        float a0 = v[j].x - mu, a1 = v[j].y - mu, a2 = v[j].z - mu, a3 = v[j].w - mu;
        var += a0 * a0 + a1 * a1 + a2 * a2 + a3 * a3;
    }
    #pragma unroll
    for (int o = 16; o; o >>= 1) var += __shfl_xor_sync(0xffffffffu, var, o);
    float inv = rsqrtf(var * (1.f / D) + 1e-6f);

    const float4* g4 = reinterpret_cast<const float4*>(g);
    const float4* b4 = reinterpret_cast<const float4*>(b);
    uint2* o8 = reinterpret_cast<uint2*>(out + (size_t)row * D);
    #pragma unroll
    for (int j = 0; j < 4; j++) {
        int c = lane + j * 32;
        float4 gg = g4[c], bb = b4[c];
        float r0 = (v[j].x - mu) * inv * gg.x + bb.x;
        float r1 = (v[j].y - mu) * inv * gg.y + bb.y;
        float r2 = (v[j].z - mu) * inv * gg.z + bb.z;
        float r3 = (v[j].w - mu) * inv * gg.w + bb.w;
        __nv_bfloat162 lo = __floats2bfloat162_rn(r0, r1);
        __nv_bfloat162 hi = __floats2bfloat162_rn(r2, r3);
        uint2 pk; pk.x = *reinterpret_cast<unsigned*>(&lo); pk.y = *reinterpret_cast<unsigned*>(&hi);
        o8[c] = pk;
    }
}

// ---------------- bf16 GEMM, 2-stage cp.async (Round-4 proven version) ----------------
#define ASTR 48
#define BSTR0 72
#define BSTR1 48
#define BSZ (64*BSTR1)

template<int TB, int OB, int MT>
__global__ __launch_bounds__(256) void wgemm(
        const bf16* __restrict__ Ag, const bf16* __restrict__ Bg,
        const float* __restrict__ bias, const float* __restrict__ res,
        void* __restrict__ Cv, int M, int N, int K, int relu,
        size_t sA, size_t sB, size_t sBias, size_t sC) {
    constexpr int WSM = MT / 32;
    constexpr int WSN = 8 / WSM;
    constexpr int NFR = 64 / (WSN * 16);
    constexpr int ASZ = MT * ASTR;

    const int z = blockIdx.z;
    const bf16* A = Ag + (size_t)z * sA;
    const bf16* B = Bg + (size_t)z * sB;
    const float* bi = bias ? bias + (size_t)z * sBias : nullptr;

    __shared__ __align__(16) char smem_raw[36864];
    bf16*  Abase = reinterpret_cast<bf16*>(smem_raw);
    bf16*  Bbase = Abase + 2 * ASZ;
    float* Cs    = reinterpret_cast<float*>(smem_raw);

    const int tid  = threadIdx.x;
    const int warp = tid >> 5;
    const int wm   = warp % WSM;
    const int wn   = warp / WSM;
    const int wnoff = wn * 16 * NFR;
    const int m0 = blockIdx.y * MT, n0 = blockIdx.x * 64;

    wmma::fragment<wmma::accumulator, 16, 16, 16, float> acc[2][NFR];
    #pragma unroll
    for (int i = 0; i < 2; i++)
        #pragma unroll
        for (int j = 0; j < NFR; j++) wmma::fill_fragment(acc[i][j], 0.f);

    auto load_stage = [&](int s, int k0) {
        bf16* As = Abase + s * ASZ;
        bf16* Bs = Bbase + s * BSZ;
        #pragma unroll
        for (int it = 0; it < MT / 64; it++) {
            int chunk = tid + it * 256;
            int r = chunk >> 2, c = (chunk & 3) << 3;
            cpa16(&As[r * ASTR + c], &A[(size_t)(m0 + r) * K + k0 + c]);
        }
        if (TB == 0) {
            int r = tid >> 3, c = (tid & 7) << 3;
            cpa16(&Bs[r * BSTR0 + c], &B[(size_t)(k0 + r) * N + n0 + c]);
        } else {
            int r = tid >> 2, c = (tid & 3) << 3;
            cpa16(&Bs[r * BSTR1 + c], &B[(size_t)(n0 + r) * K + k0 + c]);
        }
    };

    auto compute_stage = [&](int s) {
        bf16* As = Abase + s * ASZ;
        bf16* Bs = Bbase + s * BSZ;
        #pragma unroll
        for (int kk = 0; kk < 32; kk += 16) {
            wmma::fragment<wmma::matrix_a, 16, 16, 16, bf16, wmma::row_major> a0, a1;
            wmma::load_matrix_sync(a0, &As[(wm * 32 +  0) * ASTR + kk], ASTR);
            wmma::load_matrix_sync(a1, &As[(wm * 32 + 16) * ASTR + kk], ASTR);
            #pragma unroll
            for (int j = 0; j < NFR; j++) {
                if (TB == 0) {
                    wmma::fragment<wmma::matrix_b, 16, 16, 16, bf16, wmma::row_major> bf;
                    wmma::load_matrix_sync(bf, &Bs[kk * BSTR0 + wnoff + j * 16], BSTR0);
                    wmma::mma_sync(acc[0][j], a0, bf, acc[0][j]);
                    wmma::mma_sync(acc[1][j], a1, bf, acc[1][j]);
                } else {
                    wmma::fragment<wmma::matrix_b, 16, 16, 16, bf16, wmma::col_major> bf;
                    wmma::load_matrix_sync(bf, &Bs[(wnoff + j * 16) * BSTR1 + kk], BSTR1);
                    wmma::mma_sync(acc[0][j], a0, bf, acc[0][j]);
                    wmma::mma_sync(acc[1][j], a1, bf, acc[1][j]);
                }
            }
        }
    };

    const int KT = K >> 5;
    load_stage(0, 0);
    cpa_commit();
    for (int kt = 0; kt < KT; kt++) {
        if (kt + 1 < KT) { load_stage((kt + 1) & 1, (kt + 1) << 5); cpa_commit(); cpa_wait<1>(); }
        else             { cpa_wait<0>(); }
        __syncthreads();
        compute_stage(kt & 1);
        __syncthreads();
    }

    #pragma unroll
    for (int i = 0; i < 2; i++)
        #pragma unroll
        for (int j = 0; j < NFR; j++)
            wmma::store_matrix_sync(&Cs[(wm * 32 + i * 16) * 72 + wnoff + j * 16],
                                    acc[i][j], 72, wmma::mem_row_major);
    __syncthreads();

    #pragma unroll
    for (int it = 0; it < MT / 4; it++) {
        int idx = tid + it * 256;
        int r = idx >> 6, c = idx & 63;
        int m = m0 + r, n = n0 + c;
        float val = Cs[r * 72 + c];
        if (bi)   val += bi[n];
        if (relu) val = fmaxf(val, 0.f);
        if (OB) {
            reinterpret_cast<bf16*>(Cv)[(size_t)z * sC + (size_t)m * N + n] = __float2bfloat16(val);
        } else {
            float* C = reinterpret_cast<float*>(Cv) + (size_t)z * sC;
            if (res) val += res[(size_t)m * N + n];
            C[(size_t)m * N + n] = val;
        }
    }
}

// ---------------- 128x128 bf16 GEMM (high issue density) ----------------
// 256 threads, 8 warps as 4(M) x 2(N); warp tile 32x64 -> 2x4 fragments.
// EPI==0: fp32 direct store (no bias/relu).  EPI==1: bias(+relu) -> bf16 via smem halves.
#define A2STR 40
#define B2STR0 136
#define B2STR1 40

template<int TB, int EPI>
__global__ __launch_bounds__(256) void wgemm2(
        const bf16* __restrict__ Ag, const bf16* __restrict__ Bg,
        const float* __restrict__ bias, void* __restrict__ Cv,
        int M, int N, int K, int relu,
        size_t sA, size_t sB, size_t sBias, size_t sC) {
    constexpr int BST   = TB ? B2STR1 : B2STR0;
    constexpr int BROWS = TB ? 128 : 32;
    constexpr int A2SZ  = 128 * A2STR;        // 5120
    constexpr int B2SZ  = BROWS * BST;        // 5120 / 4352
    constexpr int STG2  = A2SZ + B2SZ;

    const int z = blockIdx.z;
    const bf16* A = Ag + (size_t)z * sA;
    const bf16* B = Bg + (size_t)z * sB;
    const float* bi = bias ? bias + (size_t)z * sBias : nullptr;

    __shared__ __align__(16) bf16 sm[2 * STG2];
    float* Cs = reinterpret_cast<float*>(sm);     // 64 x 136 fp32 staging (fits both TB)

    const int tid  = threadIdx.x;
    const int warp = tid >> 5;
    const int wm   = warp & 3;       // 0..3 -> rows wm*32
    const int wn   = warp >> 2;      // 0..1 -> cols wn*64
    const int m0 = blockIdx.y * 128, n0 = blockIdx.x * 128;

    wmma::fragment<wmma::accumulator, 16, 16, 16, float> acc[2][4];
    #pragma unroll
    for (int i = 0; i < 2; i++)
        #pragma unroll
        for (int j = 0; j < 4; j++) wmma::fill_fragment(acc[i][j], 0.f);

    auto load_stage = [&](int s, int k0) {
        bf16* As = sm + s * STG2;
        bf16* Bs = As + A2SZ;
        #pragma unroll
        for (int it = 0; it < 2; it++) {
            int chunk = tid + it * 256;
            int r = chunk >> 2, c = (chunk & 3) << 3;
            cpa16(&As[r * A2STR + c], &A[(size_t)(m0 + r) * K + k0 + c]);
        }
        if (TB == 0) {
            #pragma unroll
            for (int it = 0; it < 2; it++) {
                int chunk = tid + it * 256;
                int r = chunk >> 4, c = (chunk & 15) << 3;
                cpa16(&Bs[r * B2STR0 + c], &B[(size_t)(k0 + r) * N + n0 + c]);
            }
        } else {
            #pragma unroll
            for (int it = 0; it < 2; it++) {
                int chunk = tid + it * 256;
                int r = chunk >> 2, c = (chunk & 3) << 3;
                cpa16(&Bs[r * B2STR1 + c], &B[(size_t)(n0 + r) * K + k0 + c]);
            }
        }
    };

    auto compute_stage = [&](int s) {
        bf16* As = sm + s * STG2;
        bf16* Bs = As + A2SZ;
        #pragma unroll
        for (int kk = 0; kk < 32; kk += 16) {
            wmma::fragment<wmma::matrix_a, 16, 16, 16, bf16, wmma::row_major> a0, a1;
            wmma::load_matrix_sync(a0, &As[(wm * 32 +  0) * A2STR + kk], A2STR);
            wmma::load_matrix_sync(a1, &As[(wm * 32 + 16) * A2STR + kk], A2STR);
            #pragma unroll
            for (int j = 0; j < 4; j++) {
                if (TB == 0) {
                    wmma::fragment<wmma::matrix_b, 16, 16, 16, bf16, wmma::row_major> bf;
                    wmma::load_matrix_sync(bf, &Bs[kk * B2STR0 + wn * 64 + j * 16], B2STR0);
                    wmma::mma_sync(acc[0][j], a0, bf, acc[0][j]);
                    wmma::mma_sync(acc[1][j], a1, bf, acc[1][j]);
                } else {
                    wmma::fragment<wmma::matrix_b, 16, 16, 16, bf16, wmma::col_major> bf;
                    wmma::load_matrix_sync(bf, &Bs[(wn * 64 + j * 16) * B2STR1 + kk], B2STR1);
                    wmma::mma_sync(acc[0][j], a0, bf, acc[0][j]);
                    wmma::mma_sync(acc[1][j], a1, bf, acc[1][j]);
                }
            }
        }
    };

    const int KT = K >> 5;
    load_stage(0, 0);
    cpa_commit();
    for (int kt = 0; kt < KT; kt++) {
        if (kt + 1 < KT) { load_stage((kt + 1) & 1, (kt + 1) << 5); cpa_commit(); cpa_wait<1>(); }
        else             { cpa_wait<0>(); }
        __syncthreads();
        compute_stage(kt & 1);
        __syncthreads();
    }

    if (EPI == 0) {
        // direct fp32 store (final projection: no bias, no relu)
        float* C = reinterpret_cast<float*>(Cv) + (size_t)z * sC;
        #pragma unroll
        for (int i = 0; i < 2; i++)
            #pragma unroll
            for (int j = 0; j < 4; j++)
                wmma::store_matrix_sync(
                    &C[(size_t)(m0 + wm * 32 + i * 16) * N + n0 + wn * 64 + j * 16],
                    acc[i][j], N, wmma::mem_row_major);
    } else {
        // staged halves: rows [0,64) then [64,128)
        bf16* Co = reinterpret_cast<bf16*>(Cv) + (size_t)z * sC;
        #pragma unroll
        for (int hh = 0; hh < 2; hh++) {
            if ((wm >> 1) == hh) {
                #pragma unroll
                for (int i = 0; i < 2; i++)
                    #pragma unroll
                    for (int j = 0; j < 4; j++)
                        wmma::store_matrix_sync(
                            &Cs[((wm & 1) * 32 + i * 16) * 136 + wn * 64 + j * 16],
                            acc[i][j], 136, wmma::mem_row_major);
            }
            __syncthreads();
            #pragma unroll
            for (int it = 0; it < 32; it++) {
                int idx = tid + it * 256;             // 64*128 elems
                int r = idx >> 7, c = idx & 127;
                int m = m0 + hh * 64 + r, n = n0 + c;
                float val = Cs[r * 136 + c];
                if (bi)   val += bi[n];
                if (relu) val = fmaxf(val, 0.f);
                Co[(size_t)m * N + n] = __float2bfloat16(val);
            }
            __syncthreads();
        }
    }
}

// ---------------- fused flash attention ----------------
#define FA_SMEM 79872

__global__ __launch_bounds__(256) void flash_kernel(
        const bf16* __restrict__ Q, const bf16* __restrict__ Kp, const bf16* __restrict__ Vp,
        const int* __restrict__ toks, int causal, bf16* __restrict__ out) {
    extern __shared__ __align__(16) char sm[];
    bf16*  Qs = reinterpret_cast<bf16*>(sm);
    bf16*  Ks = Qs + 64 * 72;
    bf16*  Vs = Ks + 128 * 72;
    float* S  = reinterpret_cast<float*>(sm + 46080);
    bf16*  Pb = reinterpret_cast<bf16*>(sm);
    __shared__ int msk[TT];

    const int q0 = blockIdx.x * 64;
    const int h  = blockIdx.y;
    const int b  = blockIdx.z;
    const int tid = threadIdx.x, warp = tid >> 5, lane = tid & 31;

    for (int ch = tid; ch < 512; ch += 256) {
        int r = ch >> 3, c = (ch & 7) << 3;
        *reinterpret_cast<uint4*>(&Qs[r * 72 + c]) =
            *reinterpret_cast<const uint4*>(&Q[(size_t)(b * TT + q0 + r) * D + h * DK + c]);
    }
    for (int ch = tid; ch < 1024; ch += 256) {
        int r = ch >> 3, c = (ch & 7) << 3;
        *reinterpret_cast<uint4*>(&Ks[r * 72 + c]) =
            *reinterpret_cast<const uint4*>(&Kp[(size_t)(b * TT + r) * D + h * DK + c]);
        *reinterpret_cast<uint4*>(&Vs[r * 72 + c]) =
            *reinterpret_cast<const uint4*>(&Vp[(size_t)(b * TT + r) * D + h * DK + c]);
    }
    if (tid < TT) msk[tid] = (toks[b * TT + tid] == 1);
    __syncthreads();

    {
        int wm = warp & 3, wn = warp >> 2;
        #pragma unroll
        for (int n = 0; n < 4; n++) {
            wmma::fragment<wmma::accumulator, 16, 16, 16, float> acc;
            wmma::fill_fragment(acc, 0.f);
            #pragma unroll
            for (int kk = 0; kk < 4; kk++) {
                wmma::fragment<wmma::matrix_a, 16, 16, 16, bf16, wmma::row_major> a;
                wmma::fragment<wmma::matrix_b, 16, 16, 16, bf16, wmma::col_major> bb;
                wmma::load_matrix_sync(a, &Qs[(wm * 16) * 72 + kk * 16], 72);
                wmma::load_matrix_sync(bb, &Ks[(wn * 64 + n * 16) * 72 + kk * 16], 72);
                wmma::mma_sync(acc, a, bb, acc);
            }
            wmma::store_matrix_sync(&S[(wm * 16) * 132 + wn * 64 + n * 16], acc, 132,
                                    wmma::mem_row_major);
        }
    }
    __syncthreads();

    for (int rr = 0; rr < 8; rr++) {
        int r = warp * 8 + rr;
        int qg = q0 + r;
        float v[4];
        #pragma unroll
        for (int j = 0; j < 4; j++) {
            int col = lane + j * 32;
            float s = S[r * 132 + col] * 0.125f;
            if (msk[col] || (causal && col > qg)) s = -1e30f;
            v[j] = s;
        }
        float m = fmaxf(fmaxf(v[0], v[1]), fmaxf(v[2], v[3]));
        #pragma unroll
        for (int o = 16; o; o >>= 1) m = fmaxf(m, __shfl_xor_sync(0xffffffffu, m, o));
        float e[4], sum = 0.f;
        #pragma unroll
        for (int j = 0; j < 4; j++) { e[j] = __expf(v[j] - m); sum += e[j]; }
        #pragma unroll
        for (int o = 16; o; o >>= 1) sum += __shfl_xor_sync(0xffffffffu, sum, o);
        float inv = __frcp_rn(sum);
        #pragma unroll
        for (int j = 0; j < 4; j++)
            Pb[r * 136 + lane + j * 32] = __float2bfloat16(e[j] * inv);
    }
    __syncthreads();

    {
        int wm = warp & 3, wn = warp >> 2;
        #pragma unroll
        for (int n = 0; n < 2; n++) {
            wmma::fragment<wmma::accumulator, 16, 16, 16, float> acc;
            wmma::fill_fragment(acc, 0.f);
            #pragma unroll
            for (int kk = 0; kk < 8; kk++) {
                wmma::fragment<wmma::matrix_a, 16, 16, 16, bf16, wmma::row_major> a;
                wmma::fragment<wmma::matrix_b, 16, 16, 16, bf16, wmma::row_major> bb;
                wmma::load_matrix_sync(a, &Pb[(wm * 16) * 136 + kk * 16], 136);
                wmma::load_matrix_sync(bb, &Vs[(kk * 16) * 72 + wn * 32 + n * 16], 72);
                wmma::mma_sync(acc, a, bb, acc);
            }
            wmma::store_matrix_sync(&S[(wm * 16) * 132 + wn * 32 + n * 16], acc, 132,
                                    wmma::mem_row_major);
        }
    }
    __syncthreads();

    for (int idx = tid; idx < 64 * 64; idx += 256) {
        int r = idx >> 6, c = idx & 63;
        out[(size_t)(b * TT + q0 + r) * D + h * DK + c] = __float2bfloat16(S[r * 132 + c]);
    }
}

// ---------------- log_softmax (online, single read pass + write pass) ----------------
__global__ __launch_bounds__(256) void logsoftmax_kernel(float* __restrict__ logits) {
    int row = blockIdx.x;
    float* x = logits + (size_t)row * VV;
    __shared__ float shm[256], shs[256];
    int tid = threadIdx.x;

    float m = -1e30f, s = 0.f;
    for (int i = tid; i < VV / 4; i += 256) {
        float4 v = reinterpret_cast<const float4*>(x)[i];
        float cm = fmaxf(fmaxf(v.x, v.y), fmaxf(v.z, v.w));
        if (cm > m) { s *= __expf(m - cm); m = cm; }
        s += __expf(v.x - m) + __expf(v.y - m) + __expf(v.z - m) + __expf(v.w - m);
    }
    shm[tid] = m; shs[tid] = s; __syncthreads();
    for (int o = 128; o; o >>= 1) {
        if (tid < o) {
            float m2 = shm[tid + o], s2 = shs[tid + o];
            float mn = fmaxf(shm[tid], m2);
            shs[tid] = shs[tid] * __expf(shm[tid] - mn) + s2 * __expf(m2 - mn);
            shm[tid] = mn;
        }
        __syncthreads();
    }
    float lse = shm[0] + logf(shs[0]);

    for (int i = tid; i < VV / 4; i += 256) {
        float4 v = reinterpret_cast<float4*>(x)[i];
        v.x -= lse; v.y -= lse; v.z -= lse; v.w -= lse;
        reinterpret_cast<float4*>(x)[i] = v;
    }
}

// ---------------- host helpers ----------------
static void G(const bf16* A, const bf16* B, const float* bias, const float* res,
              void* C, int M, int N, int K, int relu, int tb, int ob, int mt, int batch,
              size_t sA, size_t sB, size_t sBias, size_t sC) {
    dim3 grid(N / 64, M / mt, batch);
    if (tb)           wgemm<1, 0, 128><<<grid, 256>>>(A, B, bias, res, C, M, N, K, relu, sA, sB, sBias, sC);
    else if (ob && mt == 128) wgemm<0, 1, 128><<<grid, 256>>>(A, B, bias, res, C, M, N, K, relu, sA, sB, sBias, sC);
    else if (ob)      wgemm<0, 1, 64><<<grid, 256>>>(A, B, bias, res, C, M, N, K, relu, sA, sB, sBias, sC);
    else              wgemm<0, 0, 64><<<grid, 256>>>(A, B, bias, res, C, M, N, K, relu, sA, sB, sBias, sC);
}

static void CVT(const float* s, bf16* d, size_t n) {
    int n4 = (int)(n / 4);
    f2b_kernel<<<(n4 + 255) / 256, 256>>>(s, d, n4);
}

extern "C" void kernel_launch(void* const* d_in, const int* in_sizes, int n_in,
                              void* d_out, int out_size) {
    const int*   src        = (const int*)  d_in[0];
    const int*   tgt        = (const int*)  d_in[1];
    const float* tok_emb    = (const float*)d_in[2];
    const float* pos_emb    = (const float*)d_in[3];
    const float* enc_attn_w = (const float*)d_in[4];
    const float* enc_attn_b = (const float*)d_in[5];
    const float* enc_ffn_w1 = (const float*)d_in[6];
    const float* enc_ffn_b1 = (const float*)d_in[7];
    const float* enc_ffn_w2 = (const float*)d_in[8];
    const float* enc_ffn_b2 = (const float*)d_in[9];
    const float* enc_ln     = (const float*)d_in[10];
    const float* enc_fln    = (const float*)d_in[11];
    const float* dec_attn_w = (const float*)d_in[12];
    const float* dec_attn_b = (const float*)d_in[13];
    const float* dec_ffn_w1 = (const float*)d_in[14];
    const float* dec_ffn_b1 = (const float*)d_in[15];
    const float* dec_ffn_w2 = (const float*)d_in[16];
    const float* dec_ffn_b2 = (const float*)d_in[17];
    const float* dec_ln     = (const float*)d_in[18];
    const float* dec_fln    = (const float*)d_in[19];
    float* out = (float*)d_out;

    float *x;
    bf16 *qkv, *hb, *aob, *memb, *ffnb, *kc, *vc, *wp;
    cudaGetSymbolAddress((void**)&x,    g_x);
    cudaGetSymbolAddress((void**)&qkv,  g_qkv);
    cudaGetSymbolAddress((void**)&hb,   g_hb);
    cudaGetSymbolAddress((void**)&aob,  g_aob);
    cudaGetSymbolAddress((void**)&memb, g_memb);
    cudaGetSymbolAddress((void**)&ffnb, g_ffnb);
    cudaGetSymbolAddress((void**)&kc,   g_kc);
    cudaGetSymbolAddress((void**)&vc,   g_vc);
    cudaGetSymbolAddress((void**)&wp,   g_wpool);

    cudaFuncSetAttribute(flash_kernel, cudaFuncAttributeMaxDynamicSharedMemorySize, FA_SMEM);

    const size_t DD = (size_t)D * D;
    dim3 fgrid(TT / 64, H, BBATCH);

    CVT(enc_attn_w, wp + OFF_EA,  N_EA);
    CVT(enc_ffn_w1, wp + OFF_EF1, N_EF1);
    CVT(enc_ffn_w2, wp + OFF_EF2, N_EF2);
    CVT(dec_attn_w, wp + OFF_DA,  N_DA);
    CVT(dec_ffn_w1, wp + OFF_DF1, N_DF1);
    CVT(dec_ffn_w2, wp + OFF_DF2, N_DF2);
    CVT(tok_emb,    wp + OFF_EMB, N_EMB);

    // ================= encoder =================
    embed_kernel<<<(MROWS * D + 255) / 256, 256>>>(src, tok_emb, pos_emb, x);
    for (int i = 0; i < NL; i++) {
        const bf16*  W   = wp + OFF_EA + (size_t)i * 4 * DD;
        const float* Wb  = enc_attn_b + (size_t)i * 4 * D;
        const float* lnp = enc_ln + (size_t)i * 4 * D;

        ln_kernel<<<MROWS / 8, 256>>>(x, lnp, lnp + D, hb);
        G(hb, W, Wb, nullptr, qkv, MROWS, D, D, 0, 0, 1, 128, 3, 0, DD, D, MD);
        flash_kernel<<<fgrid, 256, FA_SMEM>>>(qkv, qkv + MD, qkv + 2 * MD, src, 0, aob);
        G(aob, W + 3 * DD, Wb + 3 * D, x, x, MROWS, D, D, 0, 0, 0, 64, 1, 0, 0, 0, 0);

        ln_kernel<<<MROWS / 8, 256>>>(x, lnp + 2 * D, lnp + 3 * D, hb);
        // FFN1: 128x128 tile, bias+relu -> bf16
        wgemm2<0, 1><<<dim3(FF / 128, MROWS / 128, 1), 256>>>(
            hb, wp + OFF_EF1 + (size_t)i * D * FF, enc_ffn_b1 + (size_t)i * FF,
            ffnb, MROWS, FF, D, 1, 0, 0, 0, 0);
        G(ffnb, wp + OFF_EF2 + (size_t)i * FF * D, enc_ffn_b2 + (size_t)i * D,
          x, x, MROWS, D, FF, 0, 0, 0, 64, 1, 0, 0, 0, 0);
    }
    ln_kernel<<<MROWS / 8, 256>>>(x, enc_fln, enc_fln + D, memb);

    // cross-attention K/V for all decoder layers (batched over layers, 128x128 tile)
    wgemm2<0, 1><<<dim3(D / 128, MROWS / 128, NL), 256>>>(
        memb, wp + OFF_DA + 5 * DD, dec_attn_b + 5 * D,
        kc, MROWS, D, D, 0, 0, 8 * DD, 8 * D, MD);
    wgemm2<0, 1><<<dim3(D / 128, MROWS / 128, NL), 256>>>(
        memb, wp + OFF_DA + 6 * DD, dec_attn_b + 6 * D,
        vc, MROWS, D, D, 0, 0, 8 * DD, 8 * D, MD);

    // ================= decoder =================
    embed_kernel<<<(MROWS * D + 255) / 256, 256>>>(tgt, tok_emb, pos_emb, x);
    for (int i = 0; i < NL; i++) {
        const bf16*  W   = wp + OFF_DA + (size_t)i * 8 * DD;
        const float* Wb  = dec_attn_b + (size_t)i * 8 * D;
        const float* lnp = dec_ln + (size_t)i * 6 * D;

        // self-attention
        ln_kernel<<<MROWS / 8, 256>>>(x, lnp, lnp + D, hb);
        G(hb, W, Wb, nullptr, qkv, MROWS, D, D, 0, 0, 1, 128, 3, 0, DD, D, MD);
        flash_kernel<<<fgrid, 256, FA_SMEM>>>(qkv, qkv + MD, qkv + 2 * MD, tgt, 1, aob);
        G(aob, W + 3 * DD, Wb + 3 * D, x, x, MROWS, D, D, 0, 0, 0, 64, 1, 0, 0, 0, 0);

        // cross-attention
        ln_kernel<<<MROWS / 8, 256>>>(x, lnp + 2 * D, lnp + 3 * D, hb);
        G(hb, W + 4 * DD, Wb + 4 * D, nullptr, qkv, MROWS, D, D, 0, 0, 1, 64, 1, 0, 0, 0, 0);
        flash_kernel<<<fgrid, 256, FA_SMEM>>>(qkv, kc + (size_t)i * MD, vc + (size_t)i * MD,
                                              src, 0, aob);
        G(aob, W + 7 * DD, Wb + 7 * D, x, x, MROWS, D, D, 0, 0, 0, 64, 1, 0, 0, 0, 0);

        // FFN
        ln_kernel<<<MROWS / 8, 256>>>(x, lnp + 4 * D, lnp + 5 * D, hb);
        wgemm2<0, 1><<<dim3(FF / 128, MROWS / 128, 1), 256>>>(
            hb, wp + OFF_DF1 + (size_t)i * D * FF, dec_ffn_b1 + (size_t)i * FF,
            ffnb, MROWS, FF, D, 1, 0, 0, 0, 0);
        G(ffnb, wp + OFF_DF2 + (size_t)i * FF * D, dec_ffn_b2 + (size_t)i * D,
          x, x, MROWS, D, FF, 0, 0, 0, 64, 1, 0, 0, 0, 0);
    }
    ln_kernel<<<MROWS / 8, 256>>>(x, dec_fln, dec_fln + D, hb);

    // ============ generator: tied projection (128x128, direct fp32) + log_softmax ============
    wgemm2<1, 0><<<dim3(VV / 128, MROWS / 128, 1), 256>>>(
        hb, wp + OFF_EMB, nullptr, out, MROWS, VV, D, 0, 0, 0, 0, 0);
    logsoftmax_kernel<<<MROWS, 256>>>(out);
}